// round 4
// baseline (speedup 1.0000x reference)
#include <cuda_runtime.h>
#include <cuda_bf16.h>
#include <stdint.h>

typedef __nv_bfloat16 bf16;

#define BATCH 4
#define SEQ   2048
#define DMOD  1024

// ----------------------------------------------------------------------------
// Scratch (device globals; allocation is forbidden)
// ----------------------------------------------------------------------------
#define NQ ((long)BATCH*SEQ*DMOD)   // 8,388,608
#define NW ((long)DMOD*DMOD)        // 1,048,576
#define NS ((long)BATCH*SEQ*SEQ)    // 16,777,216

__device__ __align__(256) bf16 g_xq_hi[NQ], g_xq_lo[NQ];
__device__ __align__(256) bf16 g_xk_hi[NQ], g_xk_lo[NQ];
__device__ __align__(256) bf16 g_xv_hi[NQ], g_xv_lo[NQ];
__device__ __align__(256) bf16 g_wq_hi[NW], g_wq_lo[NW];
__device__ __align__(256) bf16 g_wk_hi[NW], g_wk_lo[NW];
__device__ __align__(256) bf16 g_wv_hi[NW], g_wv_lo[NW];
__device__ __align__(256) bf16 g_wo_hi[NW], g_wo_lo[NW];
__device__ __align__(256) bf16 g_qp_hi[NQ], g_qp_lo[NQ];
__device__ __align__(256) bf16 g_kp_hi[NQ], g_kp_lo[NQ];
__device__ __align__(256) bf16 g_vT_hi[NQ], g_vT_lo[NQ];   // vp transposed [B][D][S]
__device__ __align__(256) float g_sc[NS];                  // scores fp32
__device__ __align__(256) bf16 g_at_hi[NS], g_at_lo[NS];   // softmax probs
__device__ __align__(256) bf16 g_av_hi[NQ], g_av_lo[NQ];   // attn @ V

// ----------------------------------------------------------------------------
// helpers
// ----------------------------------------------------------------------------
__device__ __forceinline__ uint32_t smem_u32(const void* p) {
    uint32_t a;
    asm("{ .reg .u64 t; cvta.to.shared.u64 t, %1; cvt.u32.u64 %0, t; }" : "=r"(a) : "l"(p));
    return a;
}

__device__ __forceinline__ void cp16(uint32_t s, const void* g) {
    asm volatile("cp.async.cg.shared.global [%0], [%1], 16;" :: "r"(s), "l"(g));
}
#define CP_COMMIT() asm volatile("cp.async.commit_group;" ::: "memory")
#define CP_WAIT(n)  asm volatile("cp.async.wait_group %0;" :: "n"(n) : "memory")

__device__ __forceinline__ void ldsm4(uint32_t& r0, uint32_t& r1, uint32_t& r2,
                                      uint32_t& r3, uint32_t addr) {
    asm volatile("ldmatrix.sync.aligned.m8n8.x4.shared.b16 {%0,%1,%2,%3}, [%4];"
                 : "=r"(r0), "=r"(r1), "=r"(r2), "=r"(r3) : "r"(addr));
}

__device__ __forceinline__ void mma16816(float* d, const uint32_t* a, const uint32_t* b) {
    asm volatile(
        "mma.sync.aligned.m16n8k16.row.col.f32.bf16.bf16.f32 "
        "{%0,%1,%2,%3}, {%4,%5,%6,%7}, {%8,%9}, {%0,%1,%2,%3};"
        : "+f"(d[0]), "+f"(d[1]), "+f"(d[2]), "+f"(d[3])
        : "r"(a[0]), "r"(a[1]), "r"(a[2]), "r"(a[3]), "r"(b[0]), "r"(b[1]));
}

// ----------------------------------------------------------------------------
// fp32 -> bf16 hi/lo split
// ----------------------------------------------------------------------------
__global__ void split_f32(const float* __restrict__ x, bf16* __restrict__ hi,
                          bf16* __restrict__ lo, long n) {
    long i = (long)blockIdx.x * blockDim.x + threadIdx.x;
    if (i < n) {
        float v = x[i];
        bf16 h = __float2bfloat16(v);
        hi[i] = h;
        lo[i] = __float2bfloat16(v - __bfloat162float(h));
    }
}

// ----------------------------------------------------------------------------
// Row softmax fp32 -> bf16 hi/lo   (n == 2048, 256 threads)
// ----------------------------------------------------------------------------
__global__ void softmax_split(const float* __restrict__ S, bf16* __restrict__ ph,
                              bf16* __restrict__ pl, int n) {
    const float* row = S + (long)blockIdx.x * n;
    __shared__ float red[256];
    const int t = threadIdx.x;
    float e[8];
    float m = -1e30f;
#pragma unroll
    for (int i = 0; i < 8; i++) { e[i] = row[t + i * 256]; m = fmaxf(m, e[i]); }
    red[t] = m; __syncthreads();
    for (int s = 128; s > 0; s >>= 1) {
        if (t < s) red[t] = fmaxf(red[t], red[t + s]);
        __syncthreads();
    }
    m = red[0]; __syncthreads();
    float sum = 0.f;
#pragma unroll
    for (int i = 0; i < 8; i++) { e[i] = __expf(e[i] - m); sum += e[i]; }
    red[t] = sum; __syncthreads();
    for (int s = 128; s > 0; s >>= 1) {
        if (t < s) red[t] += red[t + s];
        __syncthreads();
    }
    float inv = 1.0f / red[0];
#pragma unroll
    for (int i = 0; i < 8; i++) {
        float p = e[i] * inv;
        bf16 h = __float2bfloat16(p);
        long idx = (long)blockIdx.x * n + t + i * 256;
        ph[idx] = h;
        pl[idx] = __float2bfloat16(p - __bfloat162float(h));
    }
}

// ----------------------------------------------------------------------------
// mma.sync 3xBF16 GEMM (NT):  C[m,n] = alpha * sum_k A[m,k]*B[n,k] (+ bias[n])
//   CTA tile 128x128, BK=32, 3-stage cp.async, 8 warps (64x32 each).
//   Product-major MMA order (hh, hl, lh sweeps) to break RAW chains.
// ----------------------------------------------------------------------------
#define BM 128
#define BN 128
#define BK 32
#define ROWB 80              // smem row stride bytes (32 bf16 = 64B data + 16B pad)
#define TILEB (128 * ROWB)   // 10240 B per matrix tile
#define SM_AH 0
#define SM_AL TILEB
#define SM_BH (2 * TILEB)
#define SM_BL (3 * TILEB)
#define STAGEB (4 * TILEB)   // 40960 B
#define NSTAGE 3
#define SMEM_BYTES (NSTAGE * STAGEB)

__global__ void __launch_bounds__(256) gemm3(
    const bf16* __restrict__ Ahi, const bf16* __restrict__ Alo,
    const bf16* __restrict__ Bhi, const bf16* __restrict__ Blo,
    const float* __restrict__ bias,
    float* __restrict__ Cf, bf16* __restrict__ Chi, bf16* __restrict__ Clo,
    int N, int K, int ldc, float alpha,
    long sA, long sB, long sC, int mode, int transC)
{
    extern __shared__ char smem[];
    const uint32_t sb = smem_u32(smem);
    const int tid = threadIdx.x;
    const int wid = tid >> 5;
    const int lid = tid & 31;
    const int wm = (wid & 1) * 64;       // warp M offset in CTA tile
    const int wn = (wid >> 1) * 32;      // warp N offset
    const long bz = blockIdx.z;
    const int m0 = blockIdx.y * BM;
    const int n0 = blockIdx.x * BN;

    const bf16* pAh = Ahi + bz * sA;
    const bf16* pAl = Alo + bz * sA;
    const bf16* pBh = Bhi + bz * sB;
    const bf16* pBl = Blo + bz * sB;

    const int lrow = tid >> 2;           // 0..63 base row for loads
    const int lch  = tid & 3;            // 16B chunk 0..3

    float acc[4][4][4];
#pragma unroll
    for (int i = 0; i < 4; ++i)
#pragma unroll
        for (int j = 0; j < 4; ++j)
#pragma unroll
            for (int c = 0; c < 4; ++c) acc[i][j][c] = 0.f;

    const int nch = K / BK;

    // ---- stage loader: 8 x cp.async per thread (2 rows x 4 tiles) ----
    auto issue = [&](int ch, int buf) {
        const int k0 = ch * BK;
        const uint32_t s0 = sb + buf * STAGEB;
#pragma unroll
        for (int h = 0; h < 2; ++h) {
            const int r = lrow + h * 64;
            const uint32_t so = (uint32_t)(r * ROWB + lch * 16);
            const long go = (long)r * K + k0 + lch * 8;
            cp16(s0 + SM_AH + so, pAh + (long)m0 * K + go);
            cp16(s0 + SM_AL + so, pAl + (long)m0 * K + go);
            cp16(s0 + SM_BH + so, pBh + (long)n0 * K + go);
            cp16(s0 + SM_BL + so, pBl + (long)n0 * K + go);
        }
    };

    issue(0, 0); CP_COMMIT();
    issue(1, 1); CP_COMMIT();

    // ldmatrix lane addressing (within a stage buffer)
    const int a_row = lid & 15;                    // 0..15
    const int a_col = (lid >> 4) * 16;             // 0 or 16 bytes
    const int b_nin = ((lid >> 4) & 1) * 8 + (lid & 7);  // n within 16-block
    const int b_col = ((lid >> 3) & 1) * 16;       // k-half bytes

    for (int ch = 0; ch < nch; ++ch) {
        CP_WAIT(1);
        __syncthreads();
        // refill the stage vacated at iter ch-1 (safe: barrier above orders it)
        if (ch + 2 < nch) issue(ch + 2, (ch + 2) % NSTAGE);
        CP_COMMIT();

        const uint32_t s0 = sb + (ch % NSTAGE) * STAGEB;

#pragma unroll
        for (int ks = 0; ks < 2; ++ks) {
            const int kb = ks * 32 + a_col;        // A k-byte offset for this lane
            uint32_t ah[4][4], al[4][4];
#pragma unroll
            for (int mt = 0; mt < 4; ++mt) {
                const uint32_t ro = (uint32_t)((wm + mt * 16 + a_row) * ROWB);
                ldsm4(ah[mt][0], ah[mt][1], ah[mt][2], ah[mt][3], s0 + SM_AH + ro + kb);
                ldsm4(al[mt][0], al[mt][1], al[mt][2], al[mt][3], s0 + SM_AL + ro + kb);
            }
            uint32_t bh[2][4], bl[2][4];
#pragma unroll
            for (int np = 0; np < 2; ++np) {
                const uint32_t ro = (uint32_t)((wn + np * 16 + b_nin) * ROWB + ks * 32 + b_col);
                ldsm4(bh[np][0], bh[np][1], bh[np][2], bh[np][3], s0 + SM_BH + ro);
                ldsm4(bl[np][0], bl[np][1], bl[np][2], bl[np][3], s0 + SM_BL + ro);
            }
            // product-major sweeps: 16 independent MMAs between acc reuse
#pragma unroll
            for (int mt = 0; mt < 4; ++mt)
#pragma unroll
                for (int nt = 0; nt < 4; ++nt)
                    mma16816(acc[mt][nt], ah[mt], &bh[nt >> 1][(nt & 1) * 2]);
#pragma unroll
            for (int mt = 0; mt < 4; ++mt)
#pragma unroll
                for (int nt = 0; nt < 4; ++nt)
                    mma16816(acc[mt][nt], ah[mt], &bl[nt >> 1][(nt & 1) * 2]);
#pragma unroll
            for (int mt = 0; mt < 4; ++mt)
#pragma unroll
                for (int nt = 0; nt < 4; ++nt)
                    mma16816(acc[mt][nt], al[mt], &bh[nt >> 1][(nt & 1) * 2]);
        }
    }

    // ---- epilogue ----
    const int gr = lid >> 2;             // group row 0..7
    const int tg = lid & 3;              // col pair 0..3
#pragma unroll
    for (int mt = 0; mt < 4; ++mt) {
#pragma unroll
        for (int nt = 0; nt < 4; ++nt) {
#pragma unroll
            for (int h = 0; h < 2; ++h) {        // c0c1 vs c2c3 (row +8)
                const int m = m0 + wm + mt * 16 + gr + h * 8;
#pragma unroll
                for (int c = 0; c < 2; ++c) {
                    const int n = n0 + wn + nt * 8 + tg * 2 + c;
                    float v = acc[mt][nt][h * 2 + c] * alpha;
                    if (bias) v += __ldg(bias + n);
                    if (mode == 0) {
                        Cf[bz * sC + (long)m * ldc + n] = v;
                    } else {
                        bf16 hh = __float2bfloat16(v);
                        bf16 ll = __float2bfloat16(v - __bfloat162float(hh));
                        long o = transC ? (bz * sC + (long)n * ldc + m)
                                        : (bz * sC + (long)m * ldc + n);
                        Chi[o] = hh;
                        Clo[o] = ll;
                    }
                }
            }
        }
    }
}

// ----------------------------------------------------------------------------
// launch
// ----------------------------------------------------------------------------
extern "C" void kernel_launch(void* const* d_in, const int* in_sizes, int n_in,
                              void* d_out, int out_size) {
    const float* q  = (const float*)d_in[0];
    const float* k  = (const float*)d_in[1];
    const float* v  = (const float*)d_in[2];
    const float* Wq = (const float*)d_in[3];
    const float* bq = (const float*)d_in[4];
    const float* Wk = (const float*)d_in[5];
    const float* bk = (const float*)d_in[6];
    const float* Wv = (const float*)d_in[7];
    const float* bv = (const float*)d_in[8];
    const float* Wo = (const float*)d_in[9];
    const float* bo = (const float*)d_in[10];
    float* out = (float*)d_out;

    bf16 *xqh, *xql, *xkh, *xkl, *xvh, *xvl;
    bf16 *wqh, *wql, *wkh, *wkl, *wvh, *wvl, *woh, *wol;
    bf16 *qph, *qpl, *kph, *kpl, *vTh, *vTl, *ath, *atl, *avh, *avl;
    float* sc;
    cudaGetSymbolAddress((void**)&xqh, g_xq_hi); cudaGetSymbolAddress((void**)&xql, g_xq_lo);
    cudaGetSymbolAddress((void**)&xkh, g_xk_hi); cudaGetSymbolAddress((void**)&xkl, g_xk_lo);
    cudaGetSymbolAddress((void**)&xvh, g_xv_hi); cudaGetSymbolAddress((void**)&xvl, g_xv_lo);
    cudaGetSymbolAddress((void**)&wqh, g_wq_hi); cudaGetSymbolAddress((void**)&wql, g_wq_lo);
    cudaGetSymbolAddress((void**)&wkh, g_wk_hi); cudaGetSymbolAddress((void**)&wkl, g_wk_lo);
    cudaGetSymbolAddress((void**)&wvh, g_wv_hi); cudaGetSymbolAddress((void**)&wvl, g_wv_lo);
    cudaGetSymbolAddress((void**)&woh, g_wo_hi); cudaGetSymbolAddress((void**)&wol, g_wo_lo);
    cudaGetSymbolAddress((void**)&qph, g_qp_hi); cudaGetSymbolAddress((void**)&qpl, g_qp_lo);
    cudaGetSymbolAddress((void**)&kph, g_kp_hi); cudaGetSymbolAddress((void**)&kpl, g_kp_lo);
    cudaGetSymbolAddress((void**)&vTh, g_vT_hi); cudaGetSymbolAddress((void**)&vTl, g_vT_lo);
    cudaGetSymbolAddress((void**)&ath, g_at_hi); cudaGetSymbolAddress((void**)&atl, g_at_lo);
    cudaGetSymbolAddress((void**)&avh, g_av_hi); cudaGetSymbolAddress((void**)&avl, g_av_lo);
    cudaGetSymbolAddress((void**)&sc,  g_sc);

    cudaFuncSetAttribute(gemm3, cudaFuncAttributeMaxDynamicSharedMemorySize, SMEM_BYTES);

    const int D = DMOD, S = SEQ, B = BATCH;

    split_f32<<<(unsigned)((NQ + 511) / 512), 512>>>(q, xqh, xql, NQ);
    split_f32<<<(unsigned)((NQ + 511) / 512), 512>>>(k, xkh, xkl, NQ);
    split_f32<<<(unsigned)((NQ + 511) / 512), 512>>>(v, xvh, xvl, NQ);
    split_f32<<<(unsigned)((NW + 511) / 512), 512>>>(Wq, wqh, wql, NW);
    split_f32<<<(unsigned)((NW + 511) / 512), 512>>>(Wk, wkh, wkl, NW);
    split_f32<<<(unsigned)((NW + 511) / 512), 512>>>(Wv, wvh, wvl, NW);
    split_f32<<<(unsigned)((NW + 511) / 512), 512>>>(Wo, woh, wol, NW);

    dim3 blk(256);

    // 1) q/k projections -> bf16 pair [8192, 1024]
    dim3 gp(D / BN, (B * S) / BM, 1);
    gemm3<<<gp, blk, SMEM_BYTES>>>(xqh, xql, wqh, wql, bq, nullptr, qph, qpl,
                                   D, D, D, 1.0f, 0, 0, 0, 1, 0);
    gemm3<<<gp, blk, SMEM_BYTES>>>(xkh, xkl, wkh, wkl, bk, nullptr, kph, kpl,
                                   D, D, D, 1.0f, 0, 0, 0, 1, 0);
    // v projection -> transposed bf16 pair [B][D][S]
    dim3 gv(D / BN, S / BM, B);
    gemm3<<<gv, blk, SMEM_BYTES>>>(xvh, xvl, wvh, wvl, bv, nullptr, vTh, vTl,
                                   D, D, /*ldc=*/S, 1.0f,
                                   (long)S * D, 0, (long)D * S, 1, 1);

    // 2) scores = qp @ kp^T * 0.125 -> fp32 [B,S,S]
    dim3 gs(S / BN, S / BM, B);
    gemm3<<<gs, blk, SMEM_BYTES>>>(qph, qpl, kph, kpl, nullptr, sc, nullptr, nullptr,
                                   S, D, S, 0.125f,
                                   (long)S * D, (long)S * D, (long)S * S, 0, 0);

    // 3) softmax -> bf16 pair
    softmax_split<<<(unsigned)(B * S), 256>>>(sc, ath, atl, S);

    // 4) att = attn @ vp  (NT against vT) -> bf16 pair [B,S,D]
    dim3 ga(D / BN, S / BM, B);
    gemm3<<<ga, blk, SMEM_BYTES>>>(ath, atl, vTh, vTl, nullptr, nullptr, avh, avl,
                                   D, S, D, 1.0f,
                                   (long)S * S, (long)D * S, (long)S * D, 1, 0);

    // 5) out = att @ Wo^T + bo -> fp32
    gemm3<<<gp, blk, SMEM_BYTES>>>(avh, avl, woh, wol, bo, out, nullptr, nullptr,
                                   D, D, D, 1.0f, 0, 0, 0, 0, 0);
}

// round 5
// speedup vs baseline: 1.5913x; 1.5913x over previous
#include <cuda_runtime.h>
#include <cuda_fp16.h>
#include <stdint.h>

typedef __half f16;

#define BATCH 4
#define SEQ   2048
#define DMOD  1024

// ----------------------------------------------------------------------------
// Scratch (device globals; allocation is forbidden)
// ----------------------------------------------------------------------------
#define NQ ((long)BATCH*SEQ*DMOD)   // 8,388,608
#define NW ((long)DMOD*DMOD)        // 1,048,576
#define NS ((long)BATCH*SEQ*SEQ)    // 16,777,216

__device__ __align__(256) f16 g_xq[NQ], g_xk[NQ], g_xv[NQ];        // inputs, single fp16
__device__ __align__(256) f16 g_wq_hi[NW], g_wq_lo[NW];
__device__ __align__(256) f16 g_wk_hi[NW], g_wk_lo[NW];
__device__ __align__(256) f16 g_wv_hi[NW], g_wv_lo[NW];
__device__ __align__(256) f16 g_wo_hi[NW], g_wo_lo[NW];
__device__ __align__(256) f16 g_qp[NQ];                            // q-proj, single
__device__ __align__(256) f16 g_kp_hi[NQ], g_kp_lo[NQ];            // k-proj, pair
__device__ __align__(256) f16 g_vT_hi[NQ], g_vT_lo[NQ];            // v-proj transposed [B][D][S], pair
__device__ __align__(256) float g_sc[NS];                          // scores fp32
__device__ __align__(256) f16 g_at[NS];                            // probs, single
__device__ __align__(256) f16 g_av[NQ];                            // attn@V, single

// ----------------------------------------------------------------------------
// helpers
// ----------------------------------------------------------------------------
__device__ __forceinline__ uint32_t smem_u32(const void* p) {
    uint32_t a;
    asm("{ .reg .u64 t; cvta.to.shared.u64 t, %1; cvt.u32.u64 %0, t; }" : "=r"(a) : "l"(p));
    return a;
}

__device__ __forceinline__ void cp16(uint32_t s, const void* g) {
    asm volatile("cp.async.cg.shared.global [%0], [%1], 16;" :: "r"(s), "l"(g));
}
#define CP_COMMIT() asm volatile("cp.async.commit_group;" ::: "memory")
#define CP_WAIT(n)  asm volatile("cp.async.wait_group %0;" :: "n"(n) : "memory")

__device__ __forceinline__ void ldsm4(uint32_t& r0, uint32_t& r1, uint32_t& r2,
                                      uint32_t& r3, uint32_t addr) {
    asm volatile("ldmatrix.sync.aligned.m8n8.x4.shared.b16 {%0,%1,%2,%3}, [%4];"
                 : "=r"(r0), "=r"(r1), "=r"(r2), "=r"(r3) : "r"(addr));
}

__device__ __forceinline__ void mma16816(float* d, const uint32_t* a, const uint32_t* b) {
    asm volatile(
        "mma.sync.aligned.m16n8k16.row.col.f32.f16.f16.f32 "
        "{%0,%1,%2,%3}, {%4,%5,%6,%7}, {%8,%9}, {%0,%1,%2,%3};"
        : "+f"(d[0]), "+f"(d[1]), "+f"(d[2]), "+f"(d[3])
        : "r"(a[0]), "r"(a[1]), "r"(a[2]), "r"(a[3]), "r"(b[0]), "r"(b[1]));
}

// ----------------------------------------------------------------------------
// fp32 -> fp16 (single) and fp32 -> fp16 hi/lo split
// ----------------------------------------------------------------------------
__global__ void conv_f16(const float* __restrict__ x, f16* __restrict__ y, long n) {
    long i = (long)blockIdx.x * blockDim.x + threadIdx.x;
    if (i < n) y[i] = __float2half_rn(x[i]);
}

__global__ void split_f16(const float* __restrict__ x, f16* __restrict__ hi,
                          f16* __restrict__ lo, long n) {
    long i = (long)blockIdx.x * blockDim.x + threadIdx.x;
    if (i < n) {
        float v = x[i];
        f16 h = __float2half_rn(v);
        hi[i] = h;
        lo[i] = __float2half_rn(v - __half2float(h));
    }
}

// ----------------------------------------------------------------------------
// Row softmax fp32 -> fp16   (n == 2048, 256 threads)
// ----------------------------------------------------------------------------
__global__ void softmax_f16(const float* __restrict__ S, f16* __restrict__ P, int n) {
    const float* row = S + (long)blockIdx.x * n;
    __shared__ float red[256];
    const int t = threadIdx.x;
    float e[8];
    float m = -1e30f;
#pragma unroll
    for (int i = 0; i < 8; i++) { e[i] = row[t + i * 256]; m = fmaxf(m, e[i]); }
    red[t] = m; __syncthreads();
    for (int s = 128; s > 0; s >>= 1) {
        if (t < s) red[t] = fmaxf(red[t], red[t + s]);
        __syncthreads();
    }
    m = red[0]; __syncthreads();
    float sum = 0.f;
#pragma unroll
    for (int i = 0; i < 8; i++) { e[i] = __expf(e[i] - m); sum += e[i]; }
    red[t] = sum; __syncthreads();
    for (int s = 128; s > 0; s >>= 1) {
        if (t < s) red[t] += red[t + s];
        __syncthreads();
    }
    float inv = 1.0f / red[0];
#pragma unroll
    for (int i = 0; i < 8; i++)
        P[(long)blockIdx.x * n + t + i * 256] = __float2half_rn(e[i] * inv);
}

// ----------------------------------------------------------------------------
// mma.sync fp16 2-product GEMM (NT):  C[m,n] = alpha * sum_k A[m,k]*B[n,k] (+bias)
//   A single fp16, B = Bh + Bl fp16 pair.
//   CTA tile 128x128, BK=32, double-buffered cp.async, 8 warps (64x32 each).
//   mode 0: fp32 out.  mode 1: fp16 single out.  mode 2: fp16 pair out.
// ----------------------------------------------------------------------------
#define BM 128
#define BN 128
#define BK 32
#define ROWB 80              // smem row stride bytes (32 fp16 = 64B data + 16B pad)
#define TILEB (128 * ROWB)   // 10240 B per matrix tile
#define SM_A  0
#define SM_BH TILEB
#define SM_BL (2 * TILEB)
#define STAGEB (3 * TILEB)   // 30720 B
#define SMEM_BYTES (2 * STAGEB)

__global__ void __launch_bounds__(256) gemm2(
    const f16* __restrict__ A,
    const f16* __restrict__ Bhi, const f16* __restrict__ Blo,
    const float* __restrict__ bias,
    float* __restrict__ Cf, f16* __restrict__ C1, f16* __restrict__ C2,
    int N, int K, int ldc, float alpha,
    long sA, long sB, long sC, int mode, int transC)
{
    extern __shared__ char smem[];
    const uint32_t sb = smem_u32(smem);
    const int tid = threadIdx.x;
    const int wid = tid >> 5;
    const int lid = tid & 31;
    const int wm = (wid & 1) * 64;       // warp M offset in CTA tile
    const int wn = (wid >> 1) * 32;      // warp N offset
    const long bz = blockIdx.z;
    const int m0 = blockIdx.y * BM;
    const int n0 = blockIdx.x * BN;

    const f16* pA  = A   + bz * sA;
    const f16* pBh = Bhi + bz * sB;
    const f16* pBl = Blo + bz * sB;

    const int lrow = tid >> 2;           // 0..63 base row for loads
    const int lch  = tid & 3;            // 16B chunk 0..3

    float acc[4][4][4];
#pragma unroll
    for (int i = 0; i < 4; ++i)
#pragma unroll
        for (int j = 0; j < 4; ++j)
#pragma unroll
            for (int c = 0; c < 4; ++c) acc[i][j][c] = 0.f;

    const int nch = K / BK;

    // ---- stage loader: 6 x cp.async per thread (2 rows x 3 tiles) ----
    auto issue = [&](int ch, int buf) {
        const int k0 = ch * BK;
        const uint32_t s0 = sb + buf * STAGEB;
#pragma unroll
        for (int h = 0; h < 2; ++h) {
            const int r = lrow + h * 64;
            const uint32_t so = (uint32_t)(r * ROWB + lch * 16);
            const long goA = (long)(m0 + r) * K + k0 + lch * 8;
            const long goB = (long)(n0 + r) * K + k0 + lch * 8;
            cp16(s0 + SM_A  + so, pA  + goA);
            cp16(s0 + SM_BH + so, pBh + goB);
            cp16(s0 + SM_BL + so, pBl + goB);
        }
    };

    issue(0, 0);
    CP_COMMIT();

    // ldmatrix lane addressing (within a stage buffer)
    const int a_row = lid & 15;                    // 0..15
    const int a_col = (lid >> 4) * 16;             // 0 or 16 bytes
    const int b_nin = ((lid >> 4) & 1) * 8 + (lid & 7);  // n within 16-block
    const int b_col = ((lid >> 3) & 1) * 16;       // k-half bytes

    for (int ch = 0; ch < nch; ++ch) {
        if (ch + 1 < nch) { issue(ch + 1, (ch + 1) & 1); CP_COMMIT(); CP_WAIT(1); }
        else              { CP_WAIT(0); }
        __syncthreads();

        const uint32_t s0 = sb + (ch & 1) * STAGEB;

#pragma unroll
        for (int ks = 0; ks < 2; ++ks) {
            const int kb = ks * 32 + a_col;        // A k-byte offset for this lane
            uint32_t af[4][4];
#pragma unroll
            for (int mt = 0; mt < 4; ++mt) {
                const uint32_t ro = (uint32_t)((wm + mt * 16 + a_row) * ROWB);
                ldsm4(af[mt][0], af[mt][1], af[mt][2], af[mt][3], s0 + SM_A + ro + kb);
            }
            uint32_t bh[2][4], bl[2][4];
#pragma unroll
            for (int np = 0; np < 2; ++np) {
                const uint32_t ro = (uint32_t)((wn + np * 16 + b_nin) * ROWB + ks * 32 + b_col);
                ldsm4(bh[np][0], bh[np][1], bh[np][2], bh[np][3], s0 + SM_BH + ro);
                ldsm4(bl[np][0], bl[np][1], bl[np][2], bl[np][3], s0 + SM_BL + ro);
            }
#pragma unroll
            for (int mt = 0; mt < 4; ++mt) {
#pragma unroll
                for (int nt = 0; nt < 4; ++nt) {
                    const int np = nt >> 1, sel = (nt & 1) * 2;
                    mma16816(acc[mt][nt], af[mt], &bh[np][sel]);
                    mma16816(acc[mt][nt], af[mt], &bl[np][sel]);
                }
            }
        }
        __syncthreads();
    }

    // ---- epilogue ----
    const int gr = lid >> 2;             // group row 0..7
    const int tg = lid & 3;              // col pair 0..3
#pragma unroll
    for (int mt = 0; mt < 4; ++mt) {
#pragma unroll
        for (int nt = 0; nt < 4; ++nt) {
#pragma unroll
            for (int h = 0; h < 2; ++h) {        // c0c1 vs c2c3 (row +8)
                const int m = m0 + wm + mt * 16 + gr + h * 8;
#pragma unroll
                for (int c = 0; c < 2; ++c) {
                    const int n = n0 + wn + nt * 8 + tg * 2 + c;
                    float v = acc[mt][nt][h * 2 + c] * alpha;
                    if (bias) v += __ldg(bias + n);
                    if (mode == 0) {
                        Cf[bz * sC + (long)m * ldc + n] = v;
                    } else {
                        long o = transC ? (bz * sC + (long)n * ldc + m)
                                        : (bz * sC + (long)m * ldc + n);
                        f16 hh = __float2half_rn(v);
                        C1[o] = hh;
                        if (mode == 2)
                            C2[o] = __float2half_rn(v - __half2float(hh));
                    }
                }
            }
        }
    }
}

// ----------------------------------------------------------------------------
// launch
// ----------------------------------------------------------------------------
extern "C" void kernel_launch(void* const* d_in, const int* in_sizes, int n_in,
                              void* d_out, int out_size) {
    const float* q  = (const float*)d_in[0];
    const float* k  = (const float*)d_in[1];
    const float* v  = (const float*)d_in[2];
    const float* Wq = (const float*)d_in[3];
    const float* bq = (const float*)d_in[4];
    const float* Wk = (const float*)d_in[5];
    const float* bk = (const float*)d_in[6];
    const float* Wv = (const float*)d_in[7];
    const float* bv = (const float*)d_in[8];
    const float* Wo = (const float*)d_in[9];
    const float* bo = (const float*)d_in[10];
    float* out = (float*)d_out;

    f16 *xq, *xk, *xv, *qp, *at, *av;
    f16 *wqh, *wql, *wkh, *wkl, *wvh, *wvl, *woh, *wol;
    f16 *kph, *kpl, *vTh, *vTl;
    float* sc;
    cudaGetSymbolAddress((void**)&xq, g_xq);
    cudaGetSymbolAddress((void**)&xk, g_xk);
    cudaGetSymbolAddress((void**)&xv, g_xv);
    cudaGetSymbolAddress((void**)&wqh, g_wq_hi); cudaGetSymbolAddress((void**)&wql, g_wq_lo);
    cudaGetSymbolAddress((void**)&wkh, g_wk_hi); cudaGetSymbolAddress((void**)&wkl, g_wk_lo);
    cudaGetSymbolAddress((void**)&wvh, g_wv_hi); cudaGetSymbolAddress((void**)&wvl, g_wv_lo);
    cudaGetSymbolAddress((void**)&woh, g_wo_hi); cudaGetSymbolAddress((void**)&wol, g_wo_lo);
    cudaGetSymbolAddress((void**)&qp, g_qp);
    cudaGetSymbolAddress((void**)&kph, g_kp_hi); cudaGetSymbolAddress((void**)&kpl, g_kp_lo);
    cudaGetSymbolAddress((void**)&vTh, g_vT_hi); cudaGetSymbolAddress((void**)&vTl, g_vT_lo);
    cudaGetSymbolAddress((void**)&at, g_at);
    cudaGetSymbolAddress((void**)&av, g_av);
    cudaGetSymbolAddress((void**)&sc, g_sc);

    cudaFuncSetAttribute(gemm2, cudaFuncAttributeMaxDynamicSharedMemorySize, SMEM_BYTES);

    const int D = DMOD, S = SEQ, B = BATCH;
    dim3 blk(256);
    dim3 gp(D / BN, (B * S) / BM, 1);
    dim3 gv(D / BN, S / BM, B);
    dim3 gs(S / BN, S / BM, B);
    dim3 ga(D / BN, S / BM, B);

    // Launch order chosen so launch #6 (ncu -s 5 -c 1 capture) is gemm2.
    conv_f16 <<<(unsigned)((NQ + 511) / 512), 512>>>(q, xq, NQ);               // 1
    split_f16<<<(unsigned)((NW + 511) / 512), 512>>>(Wq, wqh, wql, NW);        // 2
    conv_f16 <<<(unsigned)((NQ + 511) / 512), 512>>>(k, xk, NQ);               // 3
    split_f16<<<(unsigned)((NW + 511) / 512), 512>>>(Wk, wkh, wkl, NW);        // 4
    conv_f16 <<<(unsigned)((NQ + 511) / 512), 512>>>(v, xv, NQ);               // 5

    // 6: q projection -> qp (fp16 single)                                    <-- ncu
    gemm2<<<gp, blk, SMEM_BYTES>>>(xq, wqh, wql, bq, nullptr, qp, nullptr,
                                   D, D, D, 1.0f, 0, 0, 0, 1, 0);
    // 7: k projection -> kp (fp16 pair)
    gemm2<<<gp, blk, SMEM_BYTES>>>(xk, wkh, wkl, bk, nullptr, kph, kpl,
                                   D, D, D, 1.0f, 0, 0, 0, 2, 0);
    // 8: split Wv
    split_f16<<<(unsigned)((NW + 511) / 512), 512>>>(Wv, wvh, wvl, NW);
    // 9: v projection -> vT (fp16 pair, transposed [B][D][S])
    gemm2<<<gv, blk, SMEM_BYTES>>>(xv, wvh, wvl, bv, nullptr, vTh, vTl,
                                   D, D, /*ldc=*/S, 1.0f,
                                   (long)S * D, 0, (long)D * S, 2, 1);
    // 10: split Wo
    split_f16<<<(unsigned)((NW + 511) / 512), 512>>>(Wo, woh, wol, NW);
    // 11: scores = qp @ kp^T * 0.125 -> fp32
    gemm2<<<gs, blk, SMEM_BYTES>>>(qp, kph, kpl, nullptr, sc, nullptr, nullptr,
                                   S, D, S, 0.125f,
                                   (long)S * D, (long)S * D, (long)S * S, 0, 0);
    // 12: softmax -> fp16 probs
    softmax_f16<<<(unsigned)(B * S), 256>>>(sc, at, S);
    // 13: att = probs @ vT^T -> fp16 single
    gemm2<<<ga, blk, SMEM_BYTES>>>(at, vTh, vTl, nullptr, nullptr, av, nullptr,
                                   D, S, D, 1.0f,
                                   (long)S * S, (long)D * S, (long)S * D, 1, 0);
    // 14: out = att @ Wo^T + bo -> fp32
    gemm2<<<gp, blk, SMEM_BYTES>>>(av, woh, wol, bo, out, nullptr, nullptr,
                                   D, D, D, 1.0f, 0, 0, 0, 0, 0);
}